// round 16
// baseline (speedup 1.0000x reference)
#include <cuda_runtime.h>

// FINAL KERNEL — converged at the mixed-stream DRAM floor.
//
// Collapsed math: out[b,c] = softmax_c( d*r/1000 + d + r ),
// r = x[b,0,c], d = x[b,1,c]; logits in [0, 2.001] -> no max pass needed.
// (Full Dempster-Shafer combination cancels algebraically: e_a = d*r/K + d + r,
//  with K = NUM_CLASSES; the +1 shift is softmax-invariant.)
//
// CTA-per-row (32 threads, grid 65536) + Blackwell 256-bit global accesses:
//   - ld/st.global.cs.v8.f32 (32B/lane, 1024B/warp-request; bases 32B-aligned)
//   - 125 float8 per row per tensor: 3 unconditional iters + tail (lane<29)
//   - warp-only shfl reduction; no smem, no __syncthreads
//   - .cs streaming (zero-reuse stream)
//
// Measured: 115.2 us harness / 107.5 us kernel, DRAM 86.7%, 6875 GB/s.

#define NUM_CLASSES 1000
#define V8_PER_ROW (NUM_CLASSES / 8)       // 125 float8 per row per tensor
#define ROW_F_STRIDE (2 * NUM_CLASSES)     // 2000 floats per (2,1000) row
#define THREADS 32
#define FULL_ITERS 3                       // lane + 32*2 = 95 < 125 always

__device__ __forceinline__ void ldg256_cs(const float* p, float* v)
{
    asm("ld.global.cs.v8.f32 {%0,%1,%2,%3,%4,%5,%6,%7}, [%8];"
        : "=f"(v[0]), "=f"(v[1]), "=f"(v[2]), "=f"(v[3]),
          "=f"(v[4]), "=f"(v[5]), "=f"(v[6]), "=f"(v[7])
        : "l"(p));
}

__device__ __forceinline__ void stg256_cs(float* p, const float* v)
{
    asm volatile("st.global.cs.v8.f32 [%0], {%1,%2,%3,%4,%5,%6,%7,%8};"
        :: "l"(p),
           "f"(v[0]), "f"(v[1]), "f"(v[2]), "f"(v[3]),
           "f"(v[4]), "f"(v[5]), "f"(v[6]), "f"(v[7])
        : "memory");
}

__global__ __launch_bounds__(THREADS) void tmc_softmax_v8(
    const float* __restrict__ x, float* __restrict__ out)
{
    const int lane = threadIdx.x;
    const size_t row = blockIdx.x;

    const float* __restrict__ rgb = x + row * ROW_F_STRIDE;
    const float* __restrict__ dep = rgb + NUM_CLASSES;
    float* __restrict__ outp = out + row * NUM_CLASSES;

    const bool tail = (lane + 32 * FULL_ITERS) < V8_PER_ROW;   // lane < 29

    float ev[(FULL_ITERS + 1) * 8];
    float local = 0.f;

    #pragma unroll
    for (int i = 0; i < FULL_ITERS; i++) {
        const int idx = (lane + 32 * i) * 8;
        float r[8], d[8];
        ldg256_cs(rgb + idx, r);
        ldg256_cs(dep + idx, d);
        #pragma unroll
        for (int j = 0; j < 8; j++) {
            float e = __expf(fmaf(d[j] * r[j], 1e-3f, d[j] + r[j]));
            ev[i * 8 + j] = e;
            local += e;
        }
    }
    if (tail) {
        const int idx = (lane + 32 * FULL_ITERS) * 8;
        float r[8], d[8];
        ldg256_cs(rgb + idx, r);
        ldg256_cs(dep + idx, d);
        #pragma unroll
        for (int j = 0; j < 8; j++) {
            float e = __expf(fmaf(d[j] * r[j], 1e-3f, d[j] + r[j]));
            ev[FULL_ITERS * 8 + j] = e;
            local += e;
        }
    }

    // Warp-only reduction: no barriers, no smem.
    #pragma unroll
    for (int off = 16; off > 0; off >>= 1)
        local += __shfl_xor_sync(0xFFFFFFFFu, local, off);

    const float inv = 1.0f / local;

    #pragma unroll
    for (int i = 0; i < FULL_ITERS; i++) {
        const int idx = (lane + 32 * i) * 8;
        float o[8];
        #pragma unroll
        for (int j = 0; j < 8; j++) o[j] = ev[i * 8 + j] * inv;
        stg256_cs(outp + idx, o);
    }
    if (tail) {
        const int idx = (lane + 32 * FULL_ITERS) * 8;
        float o[8];
        #pragma unroll
        for (int j = 0; j < 8; j++) o[j] = ev[FULL_ITERS * 8 + j] * inv;
        stg256_cs(outp + idx, o);
    }
}

extern "C" void kernel_launch(void* const* d_in, const int* in_sizes, int n_in,
                              void* d_out, int out_size)
{
    const float* x = (const float*)d_in[0];
    float* out = (float*)d_out;
    const int batch = in_sizes[0] / ROW_F_STRIDE;   // 65536
    tmc_softmax_v8<<<batch, THREADS>>>(x, out);
}

// round 17
// speedup vs baseline: 1.0080x; 1.0080x over previous
#include <cuda_runtime.h>

// FINAL KERNEL — converged at the mixed-stream DRAM floor (verified twice:
// 115.2/116.2 us harness, 107.5/108.3 us kernel, DRAM 86.7/86.3%).
//
// Collapsed math: out[b,c] = softmax_c( d*r/1000 + d + r ),
// r = x[b,0,c], d = x[b,1,c]; logits in [0, 2.001] -> no max pass needed.
// (Full Dempster-Shafer combination cancels algebraically: e_a = d*r/K + d + r,
//  with K = NUM_CLASSES; the +1 shift is softmax-invariant.)
//
// CTA-per-row (32 threads, grid 65536) + Blackwell 256-bit global accesses:
//   - ld/st.global.cs.v8.f32 (32B/lane, 1024B/warp-request; bases 32B-aligned)
//   - 125 float8 per row per tensor: 3 unconditional iters + tail (lane<29)
//   - warp-only shfl reduction; no smem, no __syncthreads
//   - .cs streaming (zero-reuse stream)

#define NUM_CLASSES 1000
#define V8_PER_ROW (NUM_CLASSES / 8)       // 125 float8 per row per tensor
#define ROW_F_STRIDE (2 * NUM_CLASSES)     // 2000 floats per (2,1000) row
#define THREADS 32
#define FULL_ITERS 3                       // lane + 32*2 = 95 < 125 always

__device__ __forceinline__ void ldg256_cs(const float* p, float* v)
{
    asm("ld.global.cs.v8.f32 {%0,%1,%2,%3,%4,%5,%6,%7}, [%8];"
        : "=f"(v[0]), "=f"(v[1]), "=f"(v[2]), "=f"(v[3]),
          "=f"(v[4]), "=f"(v[5]), "=f"(v[6]), "=f"(v[7])
        : "l"(p));
}

__device__ __forceinline__ void stg256_cs(float* p, const float* v)
{
    asm volatile("st.global.cs.v8.f32 [%0], {%1,%2,%3,%4,%5,%6,%7,%8};"
        :: "l"(p),
           "f"(v[0]), "f"(v[1]), "f"(v[2]), "f"(v[3]),
           "f"(v[4]), "f"(v[5]), "f"(v[6]), "f"(v[7])
        : "memory");
}

__global__ __launch_bounds__(THREADS) void tmc_softmax_v8(
    const float* __restrict__ x, float* __restrict__ out)
{
    const int lane = threadIdx.x;
    const size_t row = blockIdx.x;

    const float* __restrict__ rgb = x + row * ROW_F_STRIDE;
    const float* __restrict__ dep = rgb + NUM_CLASSES;
    float* __restrict__ outp = out + row * NUM_CLASSES;

    const bool tail = (lane + 32 * FULL_ITERS) < V8_PER_ROW;   // lane < 29

    float ev[(FULL_ITERS + 1) * 8];
    float local = 0.f;

    #pragma unroll
    for (int i = 0; i < FULL_ITERS; i++) {
        const int idx = (lane + 32 * i) * 8;
        float r[8], d[8];
        ldg256_cs(rgb + idx, r);
        ldg256_cs(dep + idx, d);
        #pragma unroll
        for (int j = 0; j < 8; j++) {
            float e = __expf(fmaf(d[j] * r[j], 1e-3f, d[j] + r[j]));
            ev[i * 8 + j] = e;
            local += e;
        }
    }
    if (tail) {
        const int idx = (lane + 32 * FULL_ITERS) * 8;
        float r[8], d[8];
        ldg256_cs(rgb + idx, r);
        ldg256_cs(dep + idx, d);
        #pragma unroll
        for (int j = 0; j < 8; j++) {
            float e = __expf(fmaf(d[j] * r[j], 1e-3f, d[j] + r[j]));
            ev[FULL_ITERS * 8 + j] = e;
            local += e;
        }
    }

    // Warp-only reduction: no barriers, no smem.
    #pragma unroll
    for (int off = 16; off > 0; off >>= 1)
        local += __shfl_xor_sync(0xFFFFFFFFu, local, off);

    const float inv = 1.0f / local;

    #pragma unroll
    for (int i = 0; i < FULL_ITERS; i++) {
        const int idx = (lane + 32 * i) * 8;
        float o[8];
        #pragma unroll
        for (int j = 0; j < 8; j++) o[j] = ev[i * 8 + j] * inv;
        stg256_cs(outp + idx, o);
    }
    if (tail) {
        const int idx = (lane + 32 * FULL_ITERS) * 8;
        float o[8];
        #pragma unroll
        for (int j = 0; j < 8; j++) o[j] = ev[FULL_ITERS * 8 + j] * inv;
        stg256_cs(outp + idx, o);
    }
}

extern "C" void kernel_launch(void* const* d_in, const int* in_sizes, int n_in,
                              void* d_out, int out_size)
{
    const float* x = (const float*)d_in[0];
    float* out = (float*)d_out;
    const int batch = in_sizes[0] / ROW_F_STRIDE;   // 65536
    tmc_softmax_v8<<<batch, THREADS>>>(x, out);
}